// round 12
// baseline (speedup 1.0000x reference)
#include <cuda_runtime.h>
#include <cstdint>

#define NN 50000
#define EE 800000
#define DD 96
#define FF 128

// ---------------- scratch ----------------
__device__ __align__(16) float g_hA[NN * DD];
__device__ __align__(16) float g_hB[NN * DD];
__device__ __align__(16) float g_T[NN * 3 * DD];   // [N][288]: root | rel0 | rel1
__device__ __align__(16) float g_WfT[FF * DD];     // tf32-rounded, transposed Wf
__device__ __align__(16) float g_Wc[3 * DD * DD];  // tf32-rounded [root | W0 | W1]
__device__ int g_deg[2 * NN];
__device__ int g_cur[2 * NN];
__device__ int g_rowptr[2 * NN + 1];
__device__ int g_col[EE];
__device__ int g_bpart[256];

__device__ __forceinline__ uint32_t f2tf(float f) {
    uint32_t u; asm("cvt.rna.tf32.f32 %0, %1;" : "=r"(u) : "f"(f)); return u;
}
__device__ __forceinline__ float tf32r(float f) { return __uint_as_float(f2tf(f)); }

// ---------------- prep: zero deg + transpose/round Wf + round conv weights ------
__global__ void k_prep(const float* __restrict__ Wf, const float* __restrict__ root,
                       const float* __restrict__ W,
                       float* __restrict__ WfT, float* __restrict__ Wc,
                       int* __restrict__ deg, int N2) {
    int i = blockIdx.x * blockDim.x + threadIdx.x;
    if (i < N2) deg[i] = 0;
    if (i < DD * FF) {
        int d = i >> 7, k = i & 127;
        WfT[k * DD + d] = tf32r(Wf[i]);
    }
    if (i < 3 * DD * DD)
        Wc[i] = tf32r((i < DD * DD) ? root[i] : W[i - DD * DD]);
}

// ---------------- CSR build ----------------
__global__ void k_hist(const int* __restrict__ ei, const float* __restrict__ attr,
                       int* __restrict__ deg, int E) {
    int e = (blockIdx.x * blockDim.x + threadIdx.x) * 2;
    if (e >= E) return;
    int2 d2 = *(const int2*)(ei + E + e);
    float4 a4 = *(const float4*)(attr + 2 * e);
    atomicAdd(&deg[2 * d2.x + (a4.y > a4.x ? 1 : 0)], 1);
    if (e + 1 < E)
        atomicAdd(&deg[2 * d2.y + (a4.w > a4.z ? 1 : 0)], 1);
}

__global__ __launch_bounds__(1024) void k_scanA(const int* __restrict__ deg,
                                                int* __restrict__ bpart, int N2) {
    __shared__ int red[32];
    int t = threadIdx.x;
    int i = blockIdx.x * 1024 + t;
    int v = (i < N2) ? deg[i] : 0;
#pragma unroll
    for (int o = 16; o; o >>= 1) v += __shfl_down_sync(~0u, v, o);
    if ((t & 31) == 0) red[t >> 5] = v;
    __syncthreads();
    if (t < 32) {
        int s = red[t];
#pragma unroll
        for (int o = 16; o; o >>= 1) s += __shfl_down_sync(~0u, s, o);
        if (t == 0) bpart[blockIdx.x] = s;
    }
}

__global__ __launch_bounds__(1024) void k_scanC(const int* __restrict__ deg,
                                                const int* __restrict__ bpart,
                                                int* __restrict__ rowptr,
                                                int* __restrict__ cur, int N2, int nb) {
    __shared__ int sm[1024];
    __shared__ int bp[128];
    int t = threadIdx.x;
    if (t < 128) bp[t] = (t < nb) ? __ldg(&bpart[t]) : 0;
    __syncthreads();
#pragma unroll
    for (int o = 1; o < 128; o <<= 1) {
        int u = 0;
        if (t < 128 && t >= o) u = bp[t - o];
        __syncthreads();
        if (t < 128) bp[t] += u;
        __syncthreads();
    }
    int off = (blockIdx.x == 0) ? 0 : bp[blockIdx.x - 1];

    int i = blockIdx.x * 1024 + t;
    int v = (i < N2) ? deg[i] : 0;
    sm[t] = v;
    __syncthreads();
#pragma unroll
    for (int o = 1; o < 1024; o <<= 1) {
        int u = (t >= o) ? sm[t - o] : 0;
        __syncthreads();
        sm[t] += u;
        __syncthreads();
    }
    int pos = off + sm[t] - v;
    if (i < N2) {
        rowptr[i] = pos;
        cur[i] = pos;
        if (i == N2 - 1) rowptr[N2] = pos + v;
    }
}

__global__ void k_fill(const int* __restrict__ ei, const float* __restrict__ attr,
                       int* __restrict__ cur, int* __restrict__ col, int E) {
    int e = (blockIdx.x * blockDim.x + threadIdx.x) * 2;
    if (e >= E) return;
    int2 s2 = *(const int2*)(ei + e);
    int2 d2 = *(const int2*)(ei + E + e);
    float4 a4 = *(const float4*)(attr + 2 * e);
    {
        int seg = 2 * d2.x + (a4.y > a4.x ? 1 : 0);
        col[atomicAdd(&cur[seg], 1)] = s2.x;
    }
    if (e + 1 < E) {
        int seg = 2 * d2.y + (a4.w > a4.z ? 1 : 0);
        col[atomicAdd(&cur[seg], 1)] = s2.y;
    }
}

// ---------------- tf32 MMA GEMM with cp.async staging ----------------
__device__ __forceinline__ void mma_tf32(float* c, const uint32_t* a, uint32_t b0, uint32_t b1) {
    asm volatile("mma.sync.aligned.m16n8k8.row.col.f32.tf32.tf32.f32 "
        "{%0,%1,%2,%3}, {%4,%5,%6,%7}, {%8,%9}, {%0,%1,%2,%3};"
        : "+f"(c[0]), "+f"(c[1]), "+f"(c[2]), "+f"(c[3])
        : "r"(a[0]), "r"(a[1]), "r"(a[2]), "r"(a[3]), "r"(b0), "r"(b1));
}

__device__ __forceinline__ void cp16(uint32_t saddr, const void* gaddr, int srcsize) {
    asm volatile("cp.async.cg.shared.global [%0], [%1], 16, %2;"
                 :: "r"(saddr), "l"(gaddr), "r"(srcsize));
}

#define AS_LD 36
#define BS_LD 100

// flags: bit0 = relu, bit1 = round output to tf32 bits
__global__ __launch_bounds__(256, 3) void k_gemm(
    const float* __restrict__ A, int M, int K,
    const float* __restrict__ B0, const float* __restrict__ B1, const float* __restrict__ B2,
    float* __restrict__ C, int ldc, const float* __restrict__ bias, int flags)
{
    __shared__ uint32_t As[128 * AS_LD];
    __shared__ uint32_t Bs[32 * BS_LD];
    const float* B = (blockIdx.y == 0) ? B0 : ((blockIdx.y == 1) ? B1 : B2);

    int tid = threadIdx.x;
    int lane = tid & 31;
    int warp = tid >> 5;
    int g = lane >> 2, tig = lane & 3;
    int mw = warp & 3;
    int nw = warp >> 2;
    int rowblock = blockIdx.x * 128;

    uint32_t as_base = (uint32_t)__cvta_generic_to_shared(As);
    uint32_t bs_base = (uint32_t)__cvta_generic_to_shared(Bs);

    int ar[4], af[4], br_[3], bf_[3];
#pragma unroll
    for (int i = 0; i < 4; i++) { int id = tid + 256 * i; ar[i] = id >> 3; af[i] = id & 7; }
#pragma unroll
    for (int i = 0; i < 3; i++) { int id = tid + 256 * i; br_[i] = id / 24; bf_[i] = id % 24; }

    float c[2][6][4];
#pragma unroll
    for (int i = 0; i < 2; i++)
#pragma unroll
        for (int j = 0; j < 6; j++)
#pragma unroll
            for (int q = 0; q < 4; q++) c[i][j][q] = 0.f;

    for (int kb = 0; kb < K; kb += 32) {
        // stage via cp.async (zero-fill OOB rows via src-size=0)
#pragma unroll
        for (int i = 0; i < 4; i++) {
            int gr = rowblock + ar[i];
            const float* src = A + (size_t)gr * K + kb + af[i] * 4;
            uint32_t dst = as_base + (uint32_t)(ar[i] * AS_LD + af[i] * 4) * 4u;
            cp16(dst, src, (gr < M) ? 16 : 0);
        }
#pragma unroll
        for (int i = 0; i < 3; i++) {
            const float* src = B + (size_t)(kb + br_[i]) * 96 + bf_[i] * 4;
            uint32_t dst = bs_base + (uint32_t)(br_[i] * BS_LD + bf_[i] * 4) * 4u;
            cp16(dst, src, 16);
        }
        asm volatile("cp.async.commit_group;" ::: "memory");
        asm volatile("cp.async.wait_group 0;" ::: "memory");
        __syncthreads();

#pragma unroll
        for (int k8 = 0; k8 < 32; k8 += 8) {
            uint32_t a[2][4];
#pragma unroll
            for (int mt = 0; mt < 2; mt++) {
                int rb = mw * 32 + mt * 16;
                a[mt][0] = As[(rb + g) * AS_LD + k8 + tig];
                a[mt][1] = As[(rb + g + 8) * AS_LD + k8 + tig];
                a[mt][2] = As[(rb + g) * AS_LD + k8 + tig + 4];
                a[mt][3] = As[(rb + g + 8) * AS_LD + k8 + tig + 4];
            }
#pragma unroll
            for (int nt = 0; nt < 6; nt++) {
                int cb = nw * 48 + nt * 8;
                uint32_t b0 = Bs[(k8 + tig) * BS_LD + cb + g];
                uint32_t b1 = Bs[(k8 + tig + 4) * BS_LD + cb + g];
                mma_tf32(c[0][nt], a[0], b0, b1);
                mma_tf32(c[1][nt], a[1], b0, b1);
            }
        }
        __syncthreads();
    }

    int colchunk = blockIdx.y * 96;
    int relu = flags & 1, rnd = flags & 2;
#pragma unroll
    for (int mt = 0; mt < 2; mt++) {
        int r0 = rowblock + mw * 32 + mt * 16 + g;
        int r1 = r0 + 8;
#pragma unroll
        for (int nt = 0; nt < 6; nt++) {
            int col = nw * 48 + nt * 8 + 2 * tig;
            float bx = 0.f, by = 0.f;
            if (bias) { bx = __ldg(bias + col); by = __ldg(bias + col + 1); }
            float v0 = c[mt][nt][0] + bx, v1 = c[mt][nt][1] + by;
            float v2 = c[mt][nt][2] + bx, v3 = c[mt][nt][3] + by;
            if (relu) {
                v0 = fmaxf(v0, 0.f); v1 = fmaxf(v1, 0.f);
                v2 = fmaxf(v2, 0.f); v3 = fmaxf(v3, 0.f);
            }
            if (rnd) {
                v0 = tf32r(v0); v1 = tf32r(v1);
                v2 = tf32r(v2); v3 = tf32r(v3);
            }
            if (r0 < M) *(float2*)(C + (size_t)r0 * ldc + colchunk + col) = make_float2(v0, v1);
            if (r1 < M) *(float2*)(C + (size_t)r1 * ldc + colchunk + col) = make_float2(v2, v3);
        }
    }
}

// ---------------- fused float4 gather + mean + root + bias + relu ----------------
__global__ void k_aggout(const float* __restrict__ T, const int* __restrict__ rowptr,
                         const int* __restrict__ col, const float* __restrict__ bias,
                         float* __restrict__ out, int N, int roundout) {
    int warpi = (blockIdx.x * blockDim.x + threadIdx.x) >> 5;
    int lane = threadIdx.x & 31;
    if (warpi >= N) return;
    int n = warpi;
    int e00 = __ldg(&rowptr[2 * n]);
    int e01 = __ldg(&rowptr[2 * n + 1]);
    int e11 = __ldg(&rowptr[2 * n + 2]);
    int cl = (lane < 24) ? lane : 23;

    float4 x = make_float4(0.f, 0.f, 0.f, 0.f);
    float4 y = make_float4(0.f, 0.f, 0.f, 0.f);

    int e = e00;
    for (; e + 3 < e01; e += 4) {
        const float4* p0 = (const float4*)(T + (size_t)__ldg(&col[e])     * 288 + 96);
        const float4* p1 = (const float4*)(T + (size_t)__ldg(&col[e + 1]) * 288 + 96);
        const float4* p2 = (const float4*)(T + (size_t)__ldg(&col[e + 2]) * 288 + 96);
        const float4* p3 = (const float4*)(T + (size_t)__ldg(&col[e + 3]) * 288 + 96);
        float4 v0 = __ldg(p0 + cl), v1 = __ldg(p1 + cl), v2 = __ldg(p2 + cl), v3 = __ldg(p3 + cl);
        x.x += (v0.x + v1.x) + (v2.x + v3.x);
        x.y += (v0.y + v1.y) + (v2.y + v3.y);
        x.z += (v0.z + v1.z) + (v2.z + v3.z);
        x.w += (v0.w + v1.w) + (v2.w + v3.w);
    }
    for (; e < e01; e++) {
        const float4* p = (const float4*)(T + (size_t)__ldg(&col[e]) * 288 + 96);
        float4 v = __ldg(p + cl);
        x.x += v.x; x.y += v.y; x.z += v.z; x.w += v.w;
    }
    e = e01;
    for (; e + 3 < e11; e += 4) {
        const float4* p0 = (const float4*)(T + (size_t)__ldg(&col[e])     * 288 + 192);
        const float4* p1 = (const float4*)(T + (size_t)__ldg(&col[e + 1]) * 288 + 192);
        const float4* p2 = (const float4*)(T + (size_t)__ldg(&col[e + 2]) * 288 + 192);
        const float4* p3 = (const float4*)(T + (size_t)__ldg(&col[e + 3]) * 288 + 192);
        float4 v0 = __ldg(p0 + cl), v1 = __ldg(p1 + cl), v2 = __ldg(p2 + cl), v3 = __ldg(p3 + cl);
        y.x += (v0.x + v1.x) + (v2.x + v3.x);
        y.y += (v0.y + v1.y) + (v2.y + v3.y);
        y.z += (v0.z + v1.z) + (v2.z + v3.z);
        y.w += (v0.w + v1.w) + (v2.w + v3.w);
    }
    for (; e < e11; e++) {
        const float4* p = (const float4*)(T + (size_t)__ldg(&col[e]) * 288 + 192);
        float4 v = __ldg(p + cl);
        y.x += v.x; y.y += v.y; y.z += v.z; y.w += v.w;
    }

    if (lane < 24) {
        float i0 = 1.f / fmaxf((float)(e01 - e00), 1.f);
        float i1 = 1.f / fmaxf((float)(e11 - e01), 1.f);
        float4 r = __ldg((const float4*)(T + (size_t)n * 288) + lane);
        float4 b = __ldg((const float4*)bias + lane);
        float4 o;
        o.x = fmaxf(b.x + r.x + x.x * i0 + y.x * i1, 0.f);
        o.y = fmaxf(b.y + r.y + x.y * i0 + y.y * i1, 0.f);
        o.z = fmaxf(b.z + r.z + x.z * i0 + y.z * i1, 0.f);
        o.w = fmaxf(b.w + r.w + x.w * i0 + y.w * i1, 0.f);
        if (roundout) {
            o.x = tf32r(o.x); o.y = tf32r(o.y);
            o.z = tf32r(o.z); o.w = tf32r(o.w);
        }
        *((float4*)(out + (size_t)n * DD) + lane) = o;
    }
}

// ---------------- launch ----------------
extern "C" void kernel_launch(void* const* d_in, const int* in_sizes, int n_in,
                              void* d_out, int out_size) {
    const float* x    = (const float*)d_in[0];
    const int*   ei   = (const int*)d_in[1];
    const float* attr = (const float*)d_in[2];
    const float* Wf   = (const float*)d_in[3];
    const float* bf   = (const float*)d_in[4];
    const float* W    = (const float*)d_in[5];
    const float* root = (const float*)d_in[6];
    const float* bias = (const float*)d_in[7];
    float* out = (float*)d_out;

    int E = in_sizes[1] / 2;
    int N = in_sizes[0] / FF;
    int N2 = 2 * N;
    int nb = (N2 + 1023) / 1024;

    void *pA, *pB, *pT, *pWfT, *pWc, *pdg, *prp, *pc, *pcol, *pbp;
    cudaGetSymbolAddress(&pA, g_hA);
    cudaGetSymbolAddress(&pB, g_hB);
    cudaGetSymbolAddress(&pT, g_T);
    cudaGetSymbolAddress(&pWfT, g_WfT);
    cudaGetSymbolAddress(&pWc, g_Wc);
    cudaGetSymbolAddress(&pdg, g_deg);
    cudaGetSymbolAddress(&prp, g_rowptr);
    cudaGetSymbolAddress(&pc, g_cur);
    cudaGetSymbolAddress(&pcol, g_col);
    cudaGetSymbolAddress(&pbp, g_bpart);

    int mblocks = (N + 127) / 128;

    // keep GEMM as launch #4 so ncu profiles it
    k_prep<<<(N2 + 255) / 256, 256>>>(Wf, root, W, (float*)pWfT, (float*)pWc,
                                      (int*)pdg, N2);                          // 1
    k_hist<<<(E / 2 + 255) / 256, 256>>>(ei, attr, (int*)pdg, E);              // 2
    k_scanA<<<nb, 1024>>>((int*)pdg, (int*)pbp, N2);                           // 3
    // h = relu(x @ WfT + bf), rounded to tf32 bits (flags=3)
    k_gemm<<<dim3(mblocks, 1), 256>>>(x, N, FF, (const float*)pWfT, nullptr, nullptr,
                                      (float*)pA, DD, bf, 3);                  // 4 <- profiled
    k_scanC<<<nb, 1024>>>((int*)pdg, (int*)pbp, (int*)prp, (int*)pc, N2, nb);  // 5
    k_fill<<<(E / 2 + 255) / 256, 256>>>(ei, attr, (int*)pc, (int*)pcol, E);   // 6

    const float* Wc0 = (const float*)pWc;
    const float* Wc1 = Wc0 + DD * DD;
    const float* Wc2 = Wc0 + 2 * DD * DD;
    float* hin = (float*)pA;
    float* hout = (float*)pB;
    for (int it = 0; it < 3; it++) {
        // T = [h@root | h@W0 | h@W1]
        k_gemm<<<dim3(mblocks, 3), 256>>>(hin, N, DD, Wc0, Wc1, Wc2,
                                          (float*)pT, 3 * DD, nullptr, 0);
        float* o = (it == 2) ? out : hout;
        k_aggout<<<(N * 32 + 255) / 256, 256>>>((const float*)pT, (int*)prp, (int*)pcol,
                                                bias, o, N, (it < 2) ? 1 : 0);
        float* t = hin; hin = hout; hout = t;
    }
}

// round 13
// speedup vs baseline: 1.0373x; 1.0373x over previous
#include <cuda_runtime.h>
#include <cstdint>

#define NN 50000
#define EE 800000
#define DD 96
#define FF 128

// ---------------- scratch ----------------
__device__ __align__(16) float g_hA[NN * DD];
__device__ __align__(16) float g_hB[NN * DD];
__device__ __align__(16) float g_T[NN * 3 * DD];   // [N][288]: root | rel0 | rel1
__device__ __align__(16) float g_WfT[FF * DD];     // tf32-rounded, transposed Wf
__device__ __align__(16) float g_Wc[3 * DD * DD];  // tf32-rounded [root | W0 | W1]
__device__ int g_deg[2 * NN];
__device__ int g_cur[2 * NN];
__device__ int g_rowptr[2 * NN + 1];
__device__ int g_col[EE];
__device__ int g_bpart[256];

__device__ __forceinline__ uint32_t f2tf(float f) {
    uint32_t u; asm("cvt.rna.tf32.f32 %0, %1;" : "=r"(u) : "f"(f)); return u;
}
__device__ __forceinline__ float tf32r(float f) { return __uint_as_float(f2tf(f)); }

// ---------------- prep ----------------
__global__ void k_prep(const float* __restrict__ Wf, const float* __restrict__ root,
                       const float* __restrict__ W,
                       float* __restrict__ WfT, float* __restrict__ Wc,
                       int* __restrict__ deg, int N2) {
    int i = blockIdx.x * blockDim.x + threadIdx.x;
    if (i < N2) deg[i] = 0;
    if (i < DD * FF) {
        int d = i >> 7, k = i & 127;
        WfT[k * DD + d] = tf32r(Wf[i]);
    }
    if (i < 3 * DD * DD)
        Wc[i] = tf32r((i < DD * DD) ? root[i] : W[i - DD * DD]);
}

// ---------------- CSR build ----------------
__global__ void k_hist(const int* __restrict__ ei, const float* __restrict__ attr,
                       int* __restrict__ deg, int E) {
    int e = (blockIdx.x * blockDim.x + threadIdx.x) * 2;
    if (e >= E) return;
    int2 d2 = *(const int2*)(ei + E + e);
    float4 a4 = *(const float4*)(attr + 2 * e);
    atomicAdd(&deg[2 * d2.x + (a4.y > a4.x ? 1 : 0)], 1);
    if (e + 1 < E)
        atomicAdd(&deg[2 * d2.y + (a4.w > a4.z ? 1 : 0)], 1);
}

__global__ __launch_bounds__(1024) void k_scanA(const int* __restrict__ deg,
                                                int* __restrict__ bpart, int N2) {
    __shared__ int red[32];
    int t = threadIdx.x;
    int i = blockIdx.x * 1024 + t;
    int v = (i < N2) ? deg[i] : 0;
#pragma unroll
    for (int o = 16; o; o >>= 1) v += __shfl_down_sync(~0u, v, o);
    if ((t & 31) == 0) red[t >> 5] = v;
    __syncthreads();
    if (t < 32) {
        int s = red[t];
#pragma unroll
        for (int o = 16; o; o >>= 1) s += __shfl_down_sync(~0u, s, o);
        if (t == 0) bpart[blockIdx.x] = s;
    }
}

__global__ __launch_bounds__(1024) void k_scanC(const int* __restrict__ deg,
                                                const int* __restrict__ bpart,
                                                int* __restrict__ rowptr,
                                                int* __restrict__ cur, int N2, int nb) {
    __shared__ int sm[1024];
    __shared__ int bp[128];
    int t = threadIdx.x;
    if (t < 128) bp[t] = (t < nb) ? __ldg(&bpart[t]) : 0;
    __syncthreads();
#pragma unroll
    for (int o = 1; o < 128; o <<= 1) {
        int u = 0;
        if (t < 128 && t >= o) u = bp[t - o];
        __syncthreads();
        if (t < 128) bp[t] += u;
        __syncthreads();
    }
    int off = (blockIdx.x == 0) ? 0 : bp[blockIdx.x - 1];

    int i = blockIdx.x * 1024 + t;
    int v = (i < N2) ? deg[i] : 0;
    sm[t] = v;
    __syncthreads();
#pragma unroll
    for (int o = 1; o < 1024; o <<= 1) {
        int u = (t >= o) ? sm[t - o] : 0;
        __syncthreads();
        sm[t] += u;
        __syncthreads();
    }
    int pos = off + sm[t] - v;
    if (i < N2) {
        rowptr[i] = pos;
        cur[i] = pos;
        if (i == N2 - 1) rowptr[N2] = pos + v;
    }
}

__global__ void k_fill(const int* __restrict__ ei, const float* __restrict__ attr,
                       int* __restrict__ cur, int* __restrict__ col, int E) {
    int e = (blockIdx.x * blockDim.x + threadIdx.x) * 2;
    if (e >= E) return;
    int2 s2 = *(const int2*)(ei + e);
    int2 d2 = *(const int2*)(ei + E + e);
    float4 a4 = *(const float4*)(attr + 2 * e);
    {
        int seg = 2 * d2.x + (a4.y > a4.x ? 1 : 0);
        col[atomicAdd(&cur[seg], 1)] = s2.x;
    }
    if (e + 1 < E) {
        int seg = 2 * d2.y + (a4.w > a4.z ? 1 : 0);
        col[atomicAdd(&cur[seg], 1)] = s2.y;
    }
}

// ---------------- tf32 MMA GEMM: cp.async 2-stage double buffer ----------------
__device__ __forceinline__ void mma_tf32(float* c, const uint32_t* a, uint32_t b0, uint32_t b1) {
    asm volatile("mma.sync.aligned.m16n8k8.row.col.f32.tf32.tf32.f32 "
        "{%0,%1,%2,%3}, {%4,%5,%6,%7}, {%8,%9}, {%0,%1,%2,%3};"
        : "+f"(c[0]), "+f"(c[1]), "+f"(c[2]), "+f"(c[3])
        : "r"(a[0]), "r"(a[1]), "r"(a[2]), "r"(a[3]), "r"(b0), "r"(b1));
}

__device__ __forceinline__ void cp16(uint32_t saddr, const void* gaddr, int srcsize) {
    asm volatile("cp.async.cg.shared.global [%0], [%1], 16, %2;"
                 :: "r"(saddr), "l"(gaddr), "r"(srcsize));
}

#define AS_LD 36
#define BS_LD 100
#define ASZ (128 * AS_LD)
#define BSZ (32 * BS_LD)
#define GEMM_SMEM ((2 * (ASZ + BSZ)) * 4)

// flags: bit0 = relu, bit1 = round output to tf32 bits
__global__ __launch_bounds__(256, 3) void k_gemm(
    const float* __restrict__ A, int M, int K,
    const float* __restrict__ B0, const float* __restrict__ B1, const float* __restrict__ B2,
    float* __restrict__ C, int ldc, const float* __restrict__ bias, int flags)
{
    extern __shared__ uint32_t smem[];
    // layout: As[2][ASZ], Bs[2][BSZ]
    const float* B = (blockIdx.y == 0) ? B0 : ((blockIdx.y == 1) ? B1 : B2);

    int tid = threadIdx.x;
    int lane = tid & 31;
    int warp = tid >> 5;
    int g = lane >> 2, tig = lane & 3;
    int mw = warp & 3;
    int nw = warp >> 2;
    int rowblock = blockIdx.x * 128;

    uint32_t smem_base = (uint32_t)__cvta_generic_to_shared(smem);

    int ar[4], af[4], br_[3], bf_[3];
#pragma unroll
    for (int i = 0; i < 4; i++) { int id = tid + 256 * i; ar[i] = id >> 3; af[i] = id & 7; }
#pragma unroll
    for (int i = 0; i < 3; i++) { int id = tid + 256 * i; br_[i] = id / 24; bf_[i] = id % 24; }

    float c[2][6][4];
#pragma unroll
    for (int i = 0; i < 2; i++)
#pragma unroll
        for (int j = 0; j < 6; j++)
#pragma unroll
            for (int q = 0; q < 4; q++) c[i][j][q] = 0.f;

    int nk = K >> 5;   // 32-wide K chunks

    // stage chunk 0 into buffer 0
#pragma unroll
    for (int i = 0; i < 4; i++) {
        int gr = rowblock + ar[i];
        cp16(smem_base + (uint32_t)(ar[i] * AS_LD + af[i] * 4) * 4u,
             A + (size_t)gr * K + af[i] * 4, (gr < M) ? 16 : 0);
    }
#pragma unroll
    for (int i = 0; i < 3; i++) {
        cp16(smem_base + (uint32_t)(2 * ASZ + br_[i] * BS_LD + bf_[i] * 4) * 4u,
             B + (size_t)br_[i] * 96 + bf_[i] * 4, 16);
    }
    asm volatile("cp.async.commit_group;" ::: "memory");

    int buf = 0;
    for (int ck = 0; ck < nk; ck++) {
        bool more = (ck + 1 < nk);
        if (more) {
            int kb = (ck + 1) * 32;
            int nb_ = buf ^ 1;
#pragma unroll
            for (int i = 0; i < 4; i++) {
                int gr = rowblock + ar[i];
                cp16(smem_base + (uint32_t)(nb_ * ASZ + ar[i] * AS_LD + af[i] * 4) * 4u,
                     A + (size_t)gr * K + kb + af[i] * 4, (gr < M) ? 16 : 0);
            }
#pragma unroll
            for (int i = 0; i < 3; i++) {
                cp16(smem_base + (uint32_t)(2 * ASZ + nb_ * BSZ + br_[i] * BS_LD + bf_[i] * 4) * 4u,
                     B + (size_t)(kb + br_[i]) * 96 + bf_[i] * 4, 16);
            }
            asm volatile("cp.async.commit_group;" ::: "memory");
            asm volatile("cp.async.wait_group 1;" ::: "memory");
        } else {
            asm volatile("cp.async.wait_group 0;" ::: "memory");
        }
        __syncthreads();

        const uint32_t* As = smem + buf * ASZ;
        const uint32_t* Bs = smem + 2 * ASZ + buf * BSZ;
#pragma unroll
        for (int k8 = 0; k8 < 32; k8 += 8) {
            uint32_t a[2][4];
#pragma unroll
            for (int mt = 0; mt < 2; mt++) {
                int rb = mw * 32 + mt * 16;
                a[mt][0] = As[(rb + g) * AS_LD + k8 + tig];
                a[mt][1] = As[(rb + g + 8) * AS_LD + k8 + tig];
                a[mt][2] = As[(rb + g) * AS_LD + k8 + tig + 4];
                a[mt][3] = As[(rb + g + 8) * AS_LD + k8 + tig + 4];
            }
#pragma unroll
            for (int nt = 0; nt < 6; nt++) {
                int cb = nw * 48 + nt * 8;
                uint32_t b0 = Bs[(k8 + tig) * BS_LD + cb + g];
                uint32_t b1 = Bs[(k8 + tig + 4) * BS_LD + cb + g];
                mma_tf32(c[0][nt], a[0], b0, b1);
                mma_tf32(c[1][nt], a[1], b0, b1);
            }
        }
        __syncthreads();
        buf ^= 1;
    }

    int colchunk = blockIdx.y * 96;
    int relu = flags & 1, rnd = flags & 2;
#pragma unroll
    for (int mt = 0; mt < 2; mt++) {
        int r0 = rowblock + mw * 32 + mt * 16 + g;
        int r1 = r0 + 8;
#pragma unroll
        for (int nt = 0; nt < 6; nt++) {
            int col = nw * 48 + nt * 8 + 2 * tig;
            float bx = 0.f, by = 0.f;
            if (bias) { bx = __ldg(bias + col); by = __ldg(bias + col + 1); }
            float v0 = c[mt][nt][0] + bx, v1 = c[mt][nt][1] + by;
            float v2 = c[mt][nt][2] + bx, v3 = c[mt][nt][3] + by;
            if (relu) {
                v0 = fmaxf(v0, 0.f); v1 = fmaxf(v1, 0.f);
                v2 = fmaxf(v2, 0.f); v3 = fmaxf(v3, 0.f);
            }
            if (rnd) {
                v0 = tf32r(v0); v1 = tf32r(v1);
                v2 = tf32r(v2); v3 = tf32r(v3);
            }
            if (r0 < M) *(float2*)(C + (size_t)r0 * ldc + colchunk + col) = make_float2(v0, v1);
            if (r1 < M) *(float2*)(C + (size_t)r1 * ldc + colchunk + col) = make_float2(v2, v3);
        }
    }
}

// ---------------- fused float4 gather + mean + root + bias + relu ----------------
__global__ void k_aggout(const float* __restrict__ T, const int* __restrict__ rowptr,
                         const int* __restrict__ col, const float* __restrict__ bias,
                         float* __restrict__ out, int N, int roundout) {
    int warpi = (blockIdx.x * blockDim.x + threadIdx.x) >> 5;
    int lane = threadIdx.x & 31;
    if (warpi >= N) return;
    int n = warpi;
    int e00 = __ldg(&rowptr[2 * n]);
    int e01 = __ldg(&rowptr[2 * n + 1]);
    int e11 = __ldg(&rowptr[2 * n + 2]);
    int cl = (lane < 24) ? lane : 23;

    float4 x = make_float4(0.f, 0.f, 0.f, 0.f);
    float4 y = make_float4(0.f, 0.f, 0.f, 0.f);

    int e = e00;
    for (; e + 3 < e01; e += 4) {
        const float4* p0 = (const float4*)(T + (size_t)__ldg(&col[e])     * 288 + 96);
        const float4* p1 = (const float4*)(T + (size_t)__ldg(&col[e + 1]) * 288 + 96);
        const float4* p2 = (const float4*)(T + (size_t)__ldg(&col[e + 2]) * 288 + 96);
        const float4* p3 = (const float4*)(T + (size_t)__ldg(&col[e + 3]) * 288 + 96);
        float4 v0 = __ldg(p0 + cl), v1 = __ldg(p1 + cl), v2 = __ldg(p2 + cl), v3 = __ldg(p3 + cl);
        x.x += (v0.x + v1.x) + (v2.x + v3.x);
        x.y += (v0.y + v1.y) + (v2.y + v3.y);
        x.z += (v0.z + v1.z) + (v2.z + v3.z);
        x.w += (v0.w + v1.w) + (v2.w + v3.w);
    }
    for (; e < e01; e++) {
        const float4* p = (const float4*)(T + (size_t)__ldg(&col[e]) * 288 + 96);
        float4 v = __ldg(p + cl);
        x.x += v.x; x.y += v.y; x.z += v.z; x.w += v.w;
    }
    e = e01;
    for (; e + 3 < e11; e += 4) {
        const float4* p0 = (const float4*)(T + (size_t)__ldg(&col[e])     * 288 + 192);
        const float4* p1 = (const float4*)(T + (size_t)__ldg(&col[e + 1]) * 288 + 192);
        const float4* p2 = (const float4*)(T + (size_t)__ldg(&col[e + 2]) * 288 + 192);
        const float4* p3 = (const float4*)(T + (size_t)__ldg(&col[e + 3]) * 288 + 192);
        float4 v0 = __ldg(p0 + cl), v1 = __ldg(p1 + cl), v2 = __ldg(p2 + cl), v3 = __ldg(p3 + cl);
        y.x += (v0.x + v1.x) + (v2.x + v3.x);
        y.y += (v0.y + v1.y) + (v2.y + v3.y);
        y.z += (v0.z + v1.z) + (v2.z + v3.z);
        y.w += (v0.w + v1.w) + (v2.w + v3.w);
    }
    for (; e < e11; e++) {
        const float4* p = (const float4*)(T + (size_t)__ldg(&col[e]) * 288 + 192);
        float4 v = __ldg(p + cl);
        y.x += v.x; y.y += v.y; y.z += v.z; y.w += v.w;
    }

    if (lane < 24) {
        float i0 = 1.f / fmaxf((float)(e01 - e00), 1.f);
        float i1 = 1.f / fmaxf((float)(e11 - e01), 1.f);
        float4 r = __ldg((const float4*)(T + (size_t)n * 288) + lane);
        float4 b = __ldg((const float4*)bias + lane);
        float4 o;
        o.x = fmaxf(b.x + r.x + x.x * i0 + y.x * i1, 0.f);
        o.y = fmaxf(b.y + r.y + x.y * i0 + y.y * i1, 0.f);
        o.z = fmaxf(b.z + r.z + x.z * i0 + y.z * i1, 0.f);
        o.w = fmaxf(b.w + r.w + x.w * i0 + y.w * i1, 0.f);
        if (roundout) {
            o.x = tf32r(o.x); o.y = tf32r(o.y);
            o.z = tf32r(o.z); o.w = tf32r(o.w);
        }
        *((float4*)(out + (size_t)n * DD) + lane) = o;
    }
}

// ---------------- launch ----------------
extern "C" void kernel_launch(void* const* d_in, const int* in_sizes, int n_in,
                              void* d_out, int out_size) {
    const float* x    = (const float*)d_in[0];
    const int*   ei   = (const int*)d_in[1];
    const float* attr = (const float*)d_in[2];
    const float* Wf   = (const float*)d_in[3];
    const float* bf   = (const float*)d_in[4];
    const float* W    = (const float*)d_in[5];
    const float* root = (const float*)d_in[6];
    const float* bias = (const float*)d_in[7];
    float* out = (float*)d_out;

    int E = in_sizes[1] / 2;
    int N = in_sizes[0] / FF;
    int N2 = 2 * N;
    int nb = (N2 + 1023) / 1024;

    void *pA, *pB, *pT, *pWfT, *pWc, *pdg, *prp, *pc, *pcol, *pbp;
    cudaGetSymbolAddress(&pA, g_hA);
    cudaGetSymbolAddress(&pB, g_hB);
    cudaGetSymbolAddress(&pT, g_T);
    cudaGetSymbolAddress(&pWfT, g_WfT);
    cudaGetSymbolAddress(&pWc, g_Wc);
    cudaGetSymbolAddress(&pdg, g_deg);
    cudaGetSymbolAddress(&prp, g_rowptr);
    cudaGetSymbolAddress(&pc, g_cur);
    cudaGetSymbolAddress(&pcol, g_col);
    cudaGetSymbolAddress(&pbp, g_bpart);

    cudaFuncSetAttribute(k_gemm, cudaFuncAttributeMaxDynamicSharedMemorySize, GEMM_SMEM);

    int mblocks = (N + 127) / 128;

    // keep GEMM as launch #4 so ncu profiles it
    k_prep<<<(N2 + 255) / 256, 256>>>(Wf, root, W, (float*)pWfT, (float*)pWc,
                                      (int*)pdg, N2);                          // 1
    k_hist<<<(E / 2 + 255) / 256, 256>>>(ei, attr, (int*)pdg, E);              // 2
    k_scanA<<<nb, 1024>>>((int*)pdg, (int*)pbp, N2);                           // 3
    // h = relu(x @ WfT + bf), rounded to tf32 bits (flags=3)
    k_gemm<<<dim3(mblocks, 1), 256, GEMM_SMEM>>>(x, N, FF, (const float*)pWfT,
                                                 nullptr, nullptr,
                                                 (float*)pA, DD, bf, 3);       // 4 <- profiled
    k_scanC<<<nb, 1024>>>((int*)pdg, (int*)pbp, (int*)prp, (int*)pc, N2, nb);  // 5
    k_fill<<<(E / 2 + 255) / 256, 256>>>(ei, attr, (int*)pc, (int*)pcol, E);   // 6

    const float* Wc0 = (const float*)pWc;
    const float* Wc1 = Wc0 + DD * DD;
    const float* Wc2 = Wc0 + 2 * DD * DD;
    float* hin = (float*)pA;
    float* hout = (float*)pB;
    for (int it = 0; it < 3; it++) {
        // T = [h@root | h@W0 | h@W1]
        k_gemm<<<dim3(mblocks, 3), 256, GEMM_SMEM>>>(hin, N, DD, Wc0, Wc1, Wc2,
                                                     (float*)pT, 3 * DD, nullptr, 0);
        float* o = (it == 2) ? out : hout;
        k_aggout<<<(N * 32 + 255) / 256, 256>>>((const float*)pT, (int*)prp, (int*)pcol,
                                                bias, o, N, (it < 2) ? 1 : 0);
        float* t = hin; hin = hout; hout = t;
    }
}

// round 14
// speedup vs baseline: 1.2302x; 1.1860x over previous
#include <cuda_runtime.h>
#include <cuda_fp16.h>
#include <cstdint>

#define NN 50000
#define EE 800000
#define DD 96
#define FF 128

// ---------------- scratch ----------------
__device__ __align__(16) __half g_hA[NN * DD];
__device__ __align__(16) __half g_hB[NN * DD];
__device__ __align__(16) __half g_xh[NN * FF];      // fp16 copy of x
__device__ __align__(16) float  g_T[NN * 3 * DD];   // [N][288]: root | rel0 | rel1 (fp32)
__device__ __align__(16) __half g_WfT[FF * DD];     // fp16 transposed Wf
__device__ __align__(16) __half g_Wc[3 * DD * DD];  // fp16 [root | W0 | W1]
__device__ int g_deg[2 * NN];
__device__ int g_cur[2 * NN];
__device__ int g_rowptr[2 * NN + 1];
__device__ int g_col[EE];
__device__ int g_bpart[256];

// ---------------- prep: zero deg + convert/transpose weights ----------------
__global__ void k_prep(const float* __restrict__ Wf, const float* __restrict__ root,
                       const float* __restrict__ W,
                       __half* __restrict__ WfT, __half* __restrict__ Wc,
                       int* __restrict__ deg, int N2) {
    int i = blockIdx.x * blockDim.x + threadIdx.x;
    if (i < N2) deg[i] = 0;
    if (i < DD * FF) {
        int d = i >> 7, k = i & 127;
        WfT[k * DD + d] = __float2half_rn(Wf[i]);
    }
    if (i < 3 * DD * DD)
        Wc[i] = __float2half_rn((i < DD * DD) ? root[i] : W[i - DD * DD]);
}

// ---------------- x -> fp16 copy ----------------
__global__ void k_xh(const float* __restrict__ x, __half* __restrict__ xh, int total4) {
    int i = blockIdx.x * blockDim.x + threadIdx.x;
    if (i >= total4) return;
    float4 v = __ldg((const float4*)x + i);
    __half2* o = (__half2*)xh + 2 * i;
    o[0] = __floats2half2_rn(v.x, v.y);
    o[1] = __floats2half2_rn(v.z, v.w);
}

// ---------------- CSR build ----------------
__global__ void k_hist(const int* __restrict__ ei, const float* __restrict__ attr,
                       int* __restrict__ deg, int E) {
    int e = (blockIdx.x * blockDim.x + threadIdx.x) * 2;
    if (e >= E) return;
    int2 d2 = *(const int2*)(ei + E + e);
    float4 a4 = *(const float4*)(attr + 2 * e);
    atomicAdd(&deg[2 * d2.x + (a4.y > a4.x ? 1 : 0)], 1);
    if (e + 1 < E)
        atomicAdd(&deg[2 * d2.y + (a4.w > a4.z ? 1 : 0)], 1);
}

__global__ __launch_bounds__(1024) void k_scanA(const int* __restrict__ deg,
                                                int* __restrict__ bpart, int N2) {
    __shared__ int red[32];
    int t = threadIdx.x;
    int i = blockIdx.x * 1024 + t;
    int v = (i < N2) ? deg[i] : 0;
#pragma unroll
    for (int o = 16; o; o >>= 1) v += __shfl_down_sync(~0u, v, o);
    if ((t & 31) == 0) red[t >> 5] = v;
    __syncthreads();
    if (t < 32) {
        int s = red[t];
#pragma unroll
        for (int o = 16; o; o >>= 1) s += __shfl_down_sync(~0u, s, o);
        if (t == 0) bpart[blockIdx.x] = s;
    }
}

__global__ __launch_bounds__(1024) void k_scanC(const int* __restrict__ deg,
                                                const int* __restrict__ bpart,
                                                int* __restrict__ rowptr,
                                                int* __restrict__ cur, int N2, int nb) {
    __shared__ int sm[1024];
    __shared__ int bp[128];
    int t = threadIdx.x;
    if (t < 128) bp[t] = (t < nb) ? __ldg(&bpart[t]) : 0;
    __syncthreads();
#pragma unroll
    for (int o = 1; o < 128; o <<= 1) {
        int u = 0;
        if (t < 128 && t >= o) u = bp[t - o];
        __syncthreads();
        if (t < 128) bp[t] += u;
        __syncthreads();
    }
    int off = (blockIdx.x == 0) ? 0 : bp[blockIdx.x - 1];

    int i = blockIdx.x * 1024 + t;
    int v = (i < N2) ? deg[i] : 0;
    sm[t] = v;
    __syncthreads();
#pragma unroll
    for (int o = 1; o < 1024; o <<= 1) {
        int u = (t >= o) ? sm[t - o] : 0;
        __syncthreads();
        sm[t] += u;
        __syncthreads();
    }
    int pos = off + sm[t] - v;
    if (i < N2) {
        rowptr[i] = pos;
        cur[i] = pos;
        if (i == N2 - 1) rowptr[N2] = pos + v;
    }
}

__global__ void k_fill(const int* __restrict__ ei, const float* __restrict__ attr,
                       int* __restrict__ cur, int* __restrict__ col, int E) {
    int e = (blockIdx.x * blockDim.x + threadIdx.x) * 2;
    if (e >= E) return;
    int2 s2 = *(const int2*)(ei + e);
    int2 d2 = *(const int2*)(ei + E + e);
    float4 a4 = *(const float4*)(attr + 2 * e);
    {
        int seg = 2 * d2.x + (a4.y > a4.x ? 1 : 0);
        col[atomicAdd(&cur[seg], 1)] = s2.x;
    }
    if (e + 1 < E) {
        int seg = 2 * d2.y + (a4.w > a4.z ? 1 : 0);
        col[atomicAdd(&cur[seg], 1)] = s2.y;
    }
}

// ---------------- fp16 MMA GEMM: cp.async double-buffer + ldmatrix ----------------
__device__ __forceinline__ void mma_f16(float* c, const uint32_t* a, uint32_t b0, uint32_t b1) {
    asm volatile("mma.sync.aligned.m16n8k16.row.col.f32.f16.f16.f32 "
        "{%0,%1,%2,%3}, {%4,%5,%6,%7}, {%8,%9}, {%0,%1,%2,%3};"
        : "+f"(c[0]), "+f"(c[1]), "+f"(c[2]), "+f"(c[3])
        : "r"(a[0]), "r"(a[1]), "r"(a[2]), "r"(a[3]), "r"(b0), "r"(b1));
}
__device__ __forceinline__ void ldsm4(uint32_t* r, uint32_t addr) {
    asm volatile("ldmatrix.sync.aligned.m8n8.x4.shared.b16 {%0,%1,%2,%3}, [%4];"
        : "=r"(r[0]), "=r"(r[1]), "=r"(r[2]), "=r"(r[3]) : "r"(addr));
}
__device__ __forceinline__ void ldsm4t(uint32_t* r, uint32_t addr) {
    asm volatile("ldmatrix.sync.aligned.m8n8.x4.trans.shared.b16 {%0,%1,%2,%3}, [%4];"
        : "=r"(r[0]), "=r"(r[1]), "=r"(r[2]), "=r"(r[3]) : "r"(addr));
}
__device__ __forceinline__ void cp16(uint32_t saddr, const void* gaddr, int srcsize) {
    asm volatile("cp.async.cg.shared.global [%0], [%1], 16, %2;"
                 :: "r"(saddr), "l"(gaddr), "r"(srcsize));
}

#define AS_LDH 40     // halves per A smem row (80B, conflict-free for LDSM)
#define BS_LDH 104    // halves per B smem row (208B, conflict-free for LDSM.trans)
#define ASZH (128 * AS_LDH)
#define BSZH (32 * BS_LDH)
#define GEMM_SMEM ((2 * (ASZH + BSZH)) * 2)

// flags: bit0 = relu, bit2 = fp16 output (Ch), else fp32 (Cf)
__global__ __launch_bounds__(256, 3) void k_gemm(
    const __half* __restrict__ A, int M, int K,
    const __half* __restrict__ B0, const __half* __restrict__ B1, const __half* __restrict__ B2,
    float* __restrict__ Cf, __half* __restrict__ Ch, int ldc,
    const float* __restrict__ bias, int flags)
{
    extern __shared__ char smem[];
    const __half* B = (blockIdx.y == 0) ? B0 : ((blockIdx.y == 1) ? B1 : B2);

    int tid = threadIdx.x;
    int lane = tid & 31;
    int warp = tid >> 5;
    int g = lane >> 2, tig = lane & 3;
    int mw = warp & 3;
    int nw = warp >> 2;
    int rowblock = blockIdx.x * 128;

    uint32_t sbase = (uint32_t)__cvta_generic_to_shared(smem);

    float c[2][6][4];
#pragma unroll
    for (int i = 0; i < 2; i++)
#pragma unroll
        for (int j = 0; j < 6; j++)
#pragma unroll
            for (int q = 0; q < 4; q++) c[i][j][q] = 0.f;

    int nk = K >> 5;

    // --- stage chunk 0 into buffer 0 ---
#pragma unroll
    for (int i = 0; i < 2; i++) {
        int p = tid + 256 * i;               // A: 512 pieces (128 rows x 4)
        int row = p >> 2, kq = (p & 3) * 8;
        int gr = rowblock + row;
        cp16(sbase + (uint32_t)(row * AS_LDH + kq) * 2u,
             A + (size_t)gr * K + kq, (gr < M) ? 16 : 0);
    }
#pragma unroll
    for (int i = 0; i < 2; i++) {
        int p = tid + 256 * i;               // B: 384 pieces (32 rows x 12)
        if (p < 384) {
            int kr = p / 12, nq = (p % 12) * 8;
            cp16(sbase + (uint32_t)(2 * ASZH + kr * BS_LDH + nq) * 2u,
                 B + (size_t)kr * 96 + nq, 16);
        }
    }
    asm volatile("cp.async.commit_group;" ::: "memory");

    int buf = 0;
    for (int ck = 0; ck < nk; ck++) {
        bool more = (ck + 1 < nk);
        if (more) {
            int kb = (ck + 1) * 32;
            int nb_ = buf ^ 1;
#pragma unroll
            for (int i = 0; i < 2; i++) {
                int p = tid + 256 * i;
                int row = p >> 2, kq = (p & 3) * 8;
                int gr = rowblock + row;
                cp16(sbase + (uint32_t)(nb_ * ASZH + row * AS_LDH + kq) * 2u,
                     A + (size_t)gr * K + kb + kq, (gr < M) ? 16 : 0);
            }
#pragma unroll
            for (int i = 0; i < 2; i++) {
                int p = tid + 256 * i;
                if (p < 384) {
                    int kr = p / 12, nq = (p % 12) * 8;
                    cp16(sbase + (uint32_t)(2 * ASZH + nb_ * BSZH + kr * BS_LDH + nq) * 2u,
                         B + (size_t)(kb + kr) * 96 + nq, 16);
                }
            }
            asm volatile("cp.async.commit_group;" ::: "memory");
            asm volatile("cp.async.wait_group 1;" ::: "memory");
        } else {
            asm volatile("cp.async.wait_group 0;" ::: "memory");
        }
        __syncthreads();

        uint32_t abase = sbase + (uint32_t)(buf * ASZH) * 2u;
        uint32_t bbase = sbase + (uint32_t)(2 * ASZH + buf * BSZH) * 2u;
#pragma unroll
        for (int k16 = 0; k16 < 32; k16 += 16) {
            uint32_t a[2][4];
#pragma unroll
            for (int mt = 0; mt < 2; mt++) {
                int rb = mw * 32 + mt * 16;
                uint32_t addr = abase +
                    (uint32_t)((rb + (lane & 15)) * AS_LDH + k16 + ((lane >> 4) << 3)) * 2u;
                ldsm4(a[mt], addr);
            }
            uint32_t b[3][4];
#pragma unroll
            for (int ntp = 0; ntp < 3; ntp++) {
                int cb = nw * 48 + ntp * 16;
                uint32_t addr = bbase +
                    (uint32_t)((k16 + (lane & 15)) * BS_LDH + cb + ((lane & 16) ? 8 : 0)) * 2u;
                ldsm4t(b[ntp], addr);
            }
#pragma unroll
            for (int nt = 0; nt < 6; nt++) {
                uint32_t b0 = b[nt >> 1][(nt & 1) * 2];
                uint32_t b1 = b[nt >> 1][(nt & 1) * 2 + 1];
                mma_f16(c[0][nt], a[0], b0, b1);
                mma_f16(c[1][nt], a[1], b0, b1);
            }
        }
        __syncthreads();
        buf ^= 1;
    }

    int colchunk = blockIdx.y * 96;
    int relu = flags & 1, h16 = flags & 4;
#pragma unroll
    for (int mt = 0; mt < 2; mt++) {
        int r0 = rowblock + mw * 32 + mt * 16 + g;
        int r1 = r0 + 8;
#pragma unroll
        for (int nt = 0; nt < 6; nt++) {
            int col = nw * 48 + nt * 8 + 2 * tig;
            float bx = 0.f, by = 0.f;
            if (bias) { bx = __ldg(bias + col); by = __ldg(bias + col + 1); }
            float v0 = c[mt][nt][0] + bx, v1 = c[mt][nt][1] + by;
            float v2 = c[mt][nt][2] + bx, v3 = c[mt][nt][3] + by;
            if (relu) {
                v0 = fmaxf(v0, 0.f); v1 = fmaxf(v1, 0.f);
                v2 = fmaxf(v2, 0.f); v3 = fmaxf(v3, 0.f);
            }
            if (h16) {
                if (r0 < M) *(__half2*)(Ch + (size_t)r0 * ldc + col) = __floats2half2_rn(v0, v1);
                if (r1 < M) *(__half2*)(Ch + (size_t)r1 * ldc + col) = __floats2half2_rn(v2, v3);
            } else {
                if (r0 < M) *(float2*)(Cf + (size_t)r0 * ldc + colchunk + col) = make_float2(v0, v1);
                if (r1 < M) *(float2*)(Cf + (size_t)r1 * ldc + colchunk + col) = make_float2(v2, v3);
            }
        }
    }
}

// ---------------- fused float4 gather + mean + root + bias + relu ----------------
__global__ void k_aggout(const float* __restrict__ T, const int* __restrict__ rowptr,
                         const int* __restrict__ col, const float* __restrict__ bias,
                         float* __restrict__ outf, __half* __restrict__ outh,
                         int N, int tohalf) {
    int warpi = (blockIdx.x * blockDim.x + threadIdx.x) >> 5;
    int lane = threadIdx.x & 31;
    if (warpi >= N) return;
    int n = warpi;
    int e00 = __ldg(&rowptr[2 * n]);
    int e01 = __ldg(&rowptr[2 * n + 1]);
    int e11 = __ldg(&rowptr[2 * n + 2]);
    int cl = (lane < 24) ? lane : 23;

    float4 x = make_float4(0.f, 0.f, 0.f, 0.f);
    float4 y = make_float4(0.f, 0.f, 0.f, 0.f);

    int e = e00;
    for (; e + 3 < e01; e += 4) {
        const float4* p0 = (const float4*)(T + (size_t)__ldg(&col[e])     * 288 + 96);
        const float4* p1 = (const float4*)(T + (size_t)__ldg(&col[e + 1]) * 288 + 96);
        const float4* p2 = (const float4*)(T + (size_t)__ldg(&col[e + 2]) * 288 + 96);
        const float4* p3 = (const float4*)(T + (size_t)__ldg(&col[e + 3]) * 288 + 96);
        float4 v0 = __ldg(p0 + cl), v1 = __ldg(p1 + cl), v2 = __ldg(p2 + cl), v3 = __ldg(p3 + cl);
        x.x += (v0.x + v1.x) + (v2.x + v3.x);
        x.y += (v0.y + v1.y) + (v2.y + v3.y);
        x.z += (v0.z + v1.z) + (v2.z + v3.z);
        x.w += (v0.w + v1.w) + (v2.w + v3.w);
    }
    for (; e < e01; e++) {
        const float4* p = (const float4*)(T + (size_t)__ldg(&col[e]) * 288 + 96);
        float4 v = __ldg(p + cl);
        x.x += v.x; x.y += v.y; x.z += v.z; x.w += v.w;
    }
    e = e01;
    for (; e + 3 < e11; e += 4) {
        const float4* p0 = (const float4*)(T + (size_t)__ldg(&col[e])     * 288 + 192);
        const float4* p1 = (const float4*)(T + (size_t)__ldg(&col[e + 1]) * 288 + 192);
        const float4* p2 = (const float4*)(T + (size_t)__ldg(&col[e + 2]) * 288 + 192);
        const float4* p3 = (const float4*)(T + (size_t)__ldg(&col[e + 3]) * 288 + 192);
        float4 v0 = __ldg(p0 + cl), v1 = __ldg(p1 + cl), v2 = __ldg(p2 + cl), v3 = __ldg(p3 + cl);
        y.x += (v0.x + v1.x) + (v2.x + v3.x);
        y.y += (v0.y + v1.y) + (v2.y + v3.y);
        y.z += (v0.z + v1.z) + (v2.z + v3.z);
        y.w += (v0.w + v1.w) + (v2.w + v3.w);
    }
    for (; e < e11; e++) {
        const float4* p = (const float4*)(T + (size_t)__ldg(&col[e]) * 288 + 192);
        float4 v = __ldg(p + cl);
        y.x += v.x; y.y += v.y; y.z += v.z; y.w += v.w;
    }

    if (lane < 24) {
        float i0 = 1.f / fmaxf((float)(e01 - e00), 1.f);
        float i1 = 1.f / fmaxf((float)(e11 - e01), 1.f);
        float4 r = __ldg((const float4*)(T + (size_t)n * 288) + lane);
        float4 b = __ldg((const float4*)bias + lane);
        float4 o;
        o.x = fmaxf(b.x + r.x + x.x * i0 + y.x * i1, 0.f);
        o.y = fmaxf(b.y + r.y + x.y * i0 + y.y * i1, 0.f);
        o.z = fmaxf(b.z + r.z + x.z * i0 + y.z * i1, 0.f);
        o.w = fmaxf(b.w + r.w + x.w * i0 + y.w * i1, 0.f);
        if (tohalf) {
            __half* p = outh + (size_t)n * DD + 4 * lane;
            *(__half2*)p       = __floats2half2_rn(o.x, o.y);
            *(__half2*)(p + 2) = __floats2half2_rn(o.z, o.w);
        } else {
            *((float4*)(outf + (size_t)n * DD) + lane) = o;
        }
    }
}

// ---------------- launch ----------------
extern "C" void kernel_launch(void* const* d_in, const int* in_sizes, int n_in,
                              void* d_out, int out_size) {
    const float* x    = (const float*)d_in[0];
    const int*   ei   = (const int*)d_in[1];
    const float* attr = (const float*)d_in[2];
    const float* Wf   = (const float*)d_in[3];
    const float* bf   = (const float*)d_in[4];
    const float* W    = (const float*)d_in[5];
    const float* root = (const float*)d_in[6];
    const float* bias = (const float*)d_in[7];
    float* out = (float*)d_out;

    int E = in_sizes[1] / 2;
    int N = in_sizes[0] / FF;
    int N2 = 2 * N;
    int nb = (N2 + 1023) / 1024;

    void *pA, *pB, *pX, *pT, *pWfT, *pWc, *pdg, *prp, *pc, *pcol, *pbp;
    cudaGetSymbolAddress(&pA, g_hA);
    cudaGetSymbolAddress(&pB, g_hB);
    cudaGetSymbolAddress(&pX, g_xh);
    cudaGetSymbolAddress(&pT, g_T);
    cudaGetSymbolAddress(&pWfT, g_WfT);
    cudaGetSymbolAddress(&pWc, g_Wc);
    cudaGetSymbolAddress(&pdg, g_deg);
    cudaGetSymbolAddress(&prp, g_rowptr);
    cudaGetSymbolAddress(&pc, g_cur);
    cudaGetSymbolAddress(&pcol, g_col);
    cudaGetSymbolAddress(&pbp, g_bpart);

    cudaFuncSetAttribute(k_gemm, cudaFuncAttributeMaxDynamicSharedMemorySize, GEMM_SMEM);

    int mblocks = (N + 127) / 128;
    int x4 = N * FF / 4;

    // GEMM is launch #4 -> profiled by ncu
    k_prep<<<(N2 + 255) / 256, 256>>>(Wf, root, W, (__half*)pWfT, (__half*)pWc,
                                      (int*)pdg, N2);                             // 1
    k_xh<<<(x4 + 255) / 256, 256>>>(x, (__half*)pX, x4);                          // 2
    k_hist<<<(E / 2 + 255) / 256, 256>>>(ei, attr, (int*)pdg, E);                 // 3
    // h = relu(xh @ WfT + bf) -> fp16  (flags = relu | fp16out = 5)
    k_gemm<<<dim3(mblocks, 1), 256, GEMM_SMEM>>>((const __half*)pX, N, FF,
                                                 (const __half*)pWfT, nullptr, nullptr,
                                                 nullptr, (__half*)pA, DD, bf, 5); // 4 <- profiled
    k_scanA<<<nb, 1024>>>((int*)pdg, (int*)pbp, N2);                              // 5
    k_scanC<<<nb, 1024>>>((int*)pdg, (int*)pbp, (int*)prp, (int*)pc, N2, nb);     // 6
    k_fill<<<(E / 2 + 255) / 256, 256>>>(ei, attr, (int*)pc, (int*)pcol, E);      // 7

    const __half* Wc0 = (const __half*)pWc;
    const __half* Wc1 = Wc0 + DD * DD;
    const __half* Wc2 = Wc0 + 2 * DD * DD;
    __half* hin = (__half*)pA;
    __half* hout = (__half*)pB;
    for (int it = 0; it < 3; it++) {
        // T = [h@root | h@W0 | h@W1]  (fp32 out)
        k_gemm<<<dim3(mblocks, 3), 256, GEMM_SMEM>>>(hin, N, DD, Wc0, Wc1, Wc2,
                                                     (float*)pT, nullptr, 3 * DD,
                                                     nullptr, 0);
        int last = (it == 2);
        k_aggout<<<(N * 32 + 255) / 256, 256>>>((const float*)pT, (int*)prp, (int*)pcol,
                                                bias, last ? out : nullptr,
                                                last ? nullptr : hout, N, !last);
        __half* t = hin; hin = hout; hout = t;
    }
}